// round 13
// baseline (speedup 1.0000x reference)
#include <cuda_runtime.h>
#include <math.h>
#include <stdint.h>

#define KDIM   4096
#define RROWS  24
#define MAXNT  8192

// ---- fused kernel geometry (bf16 m16n8k16 dots + in-block heads + mix) ----
#define MTOK   32                 // tokens per block
#define CKM    64                 // k per chunk
#define NCHM   (KDIM / CKM)       // 64 chunks
#define NBUFM  6                  // ring depth
#define LAHD   4                  // commit-ahead distance
#define XROW   68                 // padded fp32 per x smem row
#define WROWW  36                 // padded u32 words per w smem row
#define XSZ    (MTOK * XROW * 4)  // 8704 B
#define WSZ    (RROWS * WROWW * 4)// 3456 B
#define STGB   (XSZ + WSZ)        // 12160 B
#define OFF_P  (NBUFM * STGB)             // dots partials/combined [32*24]
#define OFF_Q  (OFF_P + MTOK * RROWS * 4) // ssq [32]
#define OFF_H  (OFF_Q + MTOK * 4)         // heads [32*24]
#define SMEMD  (OFF_H + MTOK * RROWS * 4) // 79,488 B -> 2 blocks/SM

// -------- scratch (no cudaMalloc allowed) --------
__device__ uint32_t g_wB[RROWS * (KDIM / 2)];  // gamma-folded bf16x2 pairs

// ---------------- helpers ----------------
__device__ __forceinline__ void cpasync16(void* dst_smem, const void* src) {
    unsigned d = (unsigned)__cvta_generic_to_shared(dst_smem);
    asm volatile("cp.async.cg.shared.global [%0], [%1], 16;" :: "r"(d), "l"(src));
}
__device__ __forceinline__ float ex2f(float x) {
    float r; asm("ex2.approx.f32 %0, %1;" : "=f"(r) : "f"(x)); return r;
}
__device__ __forceinline__ float lg2f(float x) {
    float r; asm("lg2.approx.f32 %0, %1;" : "=f"(r) : "f"(x)); return r;
}
__device__ __forceinline__ uint32_t bf2(float2 v) {
    uint32_t r;
    asm("cvt.rn.bf16x2.f32 %0, %1, %2;" : "=r"(r) : "f"(v.y), "f"(v.x));
    return r;
}
__device__ __forceinline__ uint32_t bf2s(float lo, float hi) {
    uint32_t r;
    asm("cvt.rn.bf16x2.f32 %0, %1, %2;" : "=r"(r) : "f"(hi), "f"(lo));
    return r;
}
__device__ __forceinline__ void mma16(float* c, uint32_t a0, uint32_t a1,
                                      uint32_t a2, uint32_t a3,
                                      uint32_t b0, uint32_t b1) {
    asm volatile(
        "mma.sync.aligned.m16n8k16.row.col.f32.bf16.bf16.f32 "
        "{%0,%1,%2,%3}, {%4,%5,%6,%7}, {%8,%9}, {%0,%1,%2,%3};"
        : "+f"(c[0]), "+f"(c[1]), "+f"(c[2]), "+f"(c[3])
        : "r"(a0), "r"(a1), "r"(a2), "r"(a3), "r"(b0), "r"(b1));
}
#define LOG2E 1.4426950408889634f
__device__ __forceinline__ float lse4_2(float a, float b, float c, float d) {
    float m = fmaxf(fmaxf(a, b), fmaxf(c, d));
    float s = ex2f(a - m) + ex2f(b - m) + ex2f(c - m) + ex2f(d - m);
    return m + lg2f(s);
}

// ============================================================
// K0: fold gamma into weights, pack to bf16x2 pairs (k-major)
// ============================================================
__global__ void prep_kernel(const float* __restrict__ w_res,
                            const float* __restrict__ w_pre,
                            const float* __restrict__ w_post,
                            const float* __restrict__ gamma) {
    int idx = blockIdx.x * blockDim.x + threadIdx.x;
    if (idx >= RROWS * (KDIM / 2)) return;
    int r  = idx >> 11;
    int k  = (idx & 2047) * 2;
    const float* src;
    int rr = r;
    if (r < 16)      { src = w_res;  }
    else if (r < 20) { src = w_pre;  rr = r - 16; }
    else             { src = w_post; rr = r - 20; }
    float w0 = src[rr * KDIM + k]     * (1.0f + gamma[k]);
    float w1 = src[rr * KDIM + k + 1] * (1.0f + gamma[k + 1]);
    g_wB[idx] = bf2s(w0, w1);
}

// ============================================================
// FUSED: dots (R12 geometry, verbatim) -> heads (warp 0) ->
//        mix (x re-read is L2-hot: tile just streamed by phase 1).
// 256 blocks x 128 threads, 2 blocks/SM co-resident -> phases of the
// two blocks interleave, keeping DRAM busy.
// ============================================================
__global__ void __launch_bounds__(128, 2)
fused_kernel(const float* __restrict__ x, float* __restrict__ out,
             const float* __restrict__ beta_res,
             const float* __restrict__ beta_pre,
             const float* __restrict__ beta_post,
             const float* __restrict__ alpha_res,
             const float* __restrict__ alpha_pre,
             const float* __restrict__ alpha_post) {
    extern __shared__ __align__(16) char sm[];
    const int tid  = threadIdx.x;
    const int lane = tid & 31;
    const int warp = tid >> 5;            // 0..3
    const int mt   = warp & 1;            // m-tile
    const int grp  = warp >> 1;           // K-half of chunk
    const int g    = lane >> 2;           // 0..7
    const int tig  = lane & 3;            // 0..3
    const int tokb = blockIdx.x * MTOK;

    float* sP = (float*)(sm + OFF_P);
    float* sQ = (float*)(sm + OFF_Q);
    float* sH = (float*)(sm + OFF_H);

#define STAGE(s) do {                                                          \
        if ((s) < NCHM) {                                                      \
            char* _b = sm + ((s) % NBUFM) * STGB;                              \
            const float* _xs = x + (size_t)tokb * KDIM + (s) * CKM;            \
            _Pragma("unroll")                                                  \
            for (int _j = 0; _j < 4; ++_j) {                                   \
                int _i = tid + 128 * _j;                                       \
                int _t = _i >> 4, _c = _i & 15;                                \
                cpasync16(_b + _t * (XROW * 4) + _c * 16,                      \
                          _xs + (size_t)_t * KDIM + _c * 4);                   \
            }                                                                  \
            _Pragma("unroll")                                                  \
            for (int _j = 0; _j < 2; ++_j) {                                   \
                int _i = tid + 128 * _j;                                       \
                if (_i < 192) {                                                \
                    int _r = _i >> 3, _c = _i & 7;                             \
                    cpasync16(_b + XSZ + _r * (WROWW * 4) + _c * 16,           \
                              g_wB + _r * (KDIM / 2) + (s) * 32 + _c * 4);     \
                }                                                              \
            }                                                                  \
        }                                                                      \
        asm volatile("cp.async.commit_group;");                                \
    } while (0)

    float acc[3][4];
#pragma unroll
    for (int nt = 0; nt < 3; ++nt)
#pragma unroll
        for (int i = 0; i < 4; ++i) acc[nt][i] = 0.0f;
    float ssq0 = 0.0f, ssq1 = 0.0f;

    STAGE(0); STAGE(1); STAGE(2); STAGE(3);

    const int rowA0 = (mt * 16 + g) * XROW;
    const int rowA1 = rowA0 + 8 * XROW;

    for (int ch = 0; ch < NCHM; ++ch) {
        STAGE(ch + LAHD);
        asm volatile("cp.async.wait_group %0;" :: "n"(LAHD) : "memory");
        __syncthreads();

        const float*    xb = (const float*)(sm + (ch % NBUFM) * STGB);
        const uint32_t* wb = (const uint32_t*)((const char*)xb + XSZ);

#pragma unroll
        for (int kt = 0; kt < 2; ++kt) {
            const int kb = grp * 32 + kt * 16 + 2 * tig;
            float2 f0 = *(const float2*)(xb + rowA0 + kb);
            float2 f1 = *(const float2*)(xb + rowA1 + kb);
            float2 f2 = *(const float2*)(xb + rowA0 + kb + 8);
            float2 f3 = *(const float2*)(xb + rowA1 + kb + 8);
            ssq0 = fmaf(f0.x, f0.x, fmaf(f0.y, f0.y,
                   fmaf(f2.x, f2.x, fmaf(f2.y, f2.y, ssq0))));
            ssq1 = fmaf(f1.x, f1.x, fmaf(f1.y, f1.y,
                   fmaf(f3.x, f3.x, fmaf(f3.y, f3.y, ssq1))));
            uint32_t A0 = bf2(f0), A1 = bf2(f1), A2 = bf2(f2), A3 = bf2(f3);
            const int wbase = grp * 16 + kt * 8 + tig;
#pragma unroll
            for (int nt = 0; nt < 3; ++nt) {
                const uint32_t* wr = wb + (nt * 8 + g) * WROWW + wbase;
                mma16(acc[nt], A0, A1, A2, A3, wr[0], wr[4]);
            }
        }
    }

    // ---- quad-reduce ssq ----
    ssq0 += __shfl_down_sync(0xffffffffu, ssq0, 2, 4);
    ssq0 += __shfl_down_sync(0xffffffffu, ssq0, 1, 4);
    ssq1 += __shfl_down_sync(0xffffffffu, ssq1, 2, 4);
    ssq1 += __shfl_down_sync(0xffffffffu, ssq1, 1, 4);

    const int t0l = mt * 16 + g;
    const int t1l = t0l + 8;

    // ---- combine K-half partials in smem ----
    __syncthreads();
    if (grp == 1) {
#pragma unroll
        for (int nt = 0; nt < 3; ++nt) {
            int r = nt * 8 + 2 * tig;
            *(float2*)(sP + t0l * RROWS + r) = make_float2(acc[nt][0], acc[nt][1]);
            *(float2*)(sP + t1l * RROWS + r) = make_float2(acc[nt][2], acc[nt][3]);
        }
        if (tig == 0) { sQ[t0l] = ssq0; sQ[t1l] = ssq1; }
    }
    __syncthreads();
    if (grp == 0) {
#pragma unroll
        for (int nt = 0; nt < 3; ++nt) {
            int r = nt * 8 + 2 * tig;
            float2 p0 = *(const float2*)(sP + t0l * RROWS + r);
            float2 p1 = *(const float2*)(sP + t1l * RROWS + r);
            *(float2*)(sP + t0l * RROWS + r) =
                make_float2(acc[nt][0] + p0.x, acc[nt][1] + p0.y);
            *(float2*)(sP + t1l * RROWS + r) =
                make_float2(acc[nt][2] + p1.x, acc[nt][3] + p1.y);
        }
        if (tig == 0) {
            sQ[t0l] = ssq0 + sQ[t0l];
            sQ[t1l] = ssq1 + sQ[t1l];
        }
    }
    __syncthreads();

    // ---- heads: warp 0, one thread per token ----
    if (tid < MTOK) {
        const int t = tid;
        float rstd = 64.0f / fmaxf(sqrtf(sQ[t]), 1e-12f);
        const float* dp = sP + t * RROWS;
        float ar = alpha_res[0]  * rstd;
        float ap = alpha_pre[0]  * rstd;
        float ao = alpha_post[0] * rstd;

        float Z[16];
#pragma unroll
        for (int e = 0; e < 16; ++e)
            Z[e] = (beta_res[e] + ar * dp[e]) * (20.0f * LOG2E);

        float u[4] = {0.f, 0.f, 0.f, 0.f};
        float v[4] = {0.f, 0.f, 0.f, 0.f};
#pragma unroll 1
        for (int itn = 0; itn < 10; ++itn) {
#pragma unroll
            for (int i = 0; i < 4; ++i)
                u[i] = -lse4_2(Z[i*4+0] + v[0], Z[i*4+1] + v[1],
                               Z[i*4+2] + v[2], Z[i*4+3] + v[3]);
#pragma unroll
            for (int j = 0; j < 4; ++j)
                v[j] = -lse4_2(Z[0*4+j] + u[0], Z[1*4+j] + u[1],
                               Z[2*4+j] + u[2], Z[3*4+j] + u[3]);
        }

        float* hp = sH + t * RROWS;
#pragma unroll
        for (int i = 0; i < 4; ++i)
#pragma unroll
            for (int j = 0; j < 4; ++j)
                hp[i*4+j] = ex2f(Z[i*4+j] + u[i] + v[j]);

        float p[4];
#pragma unroll
        for (int s = 0; s < 4; ++s)
            p[s] = (beta_pre[s] + ap * dp[16 + s]) * LOG2E;
        float m = fmaxf(fmaxf(p[0], p[1]), fmaxf(p[2], p[3]));
        float e0 = ex2f(p[0]-m), e1 = ex2f(p[1]-m);
        float e2 = ex2f(p[2]-m), e3 = ex2f(p[3]-m);
        float inv = 1.0f / (e0 + e1 + e2 + e3);
        hp[16] = e0*inv; hp[17] = e1*inv; hp[18] = e2*inv; hp[19] = e3*inv;

#pragma unroll
        for (int s = 0; s < 4; ++s) {
            float q = beta_post[s] + ao * dp[20 + s];
            hp[20 + s] = 2.0f / (1.0f + ex2f(-q * LOG2E));
        }
    }
    __syncthreads();

    // ---- mix: re-read own x tile (L2-hot), write out ----
    const int seg = tid * 8;              // 128 thr x 8 floats = 1024 = D
#pragma unroll 1
    for (int t = 0; t < MTOK; ++t) {
        const float* hp = sH + t * RROWS;
        const float* xr = x   + (size_t)(tokb + t) * KDIM + seg;
        float*       yr = out + (size_t)(tokb + t) * KDIM + seg;

        float4 xj[4][2];
#pragma unroll
        for (int j = 0; j < 4; ++j) {
            xj[j][0] = *(const float4*)(xr + j * 1024);
            xj[j][1] = *(const float4*)(xr + j * 1024 + 4);
        }

        float hp0 = hp[16], hp1 = hp[17], hp2 = hp[18], hp3 = hp[19];
        float4 bin[2];
#pragma unroll
        for (int q = 0; q < 2; ++q) {
            bin[q].x = hp0*xj[0][q].x + hp1*xj[1][q].x + hp2*xj[2][q].x + hp3*xj[3][q].x;
            bin[q].y = hp0*xj[0][q].y + hp1*xj[1][q].y + hp2*xj[2][q].y + hp3*xj[3][q].y;
            bin[q].z = hp0*xj[0][q].z + hp1*xj[1][q].z + hp2*xj[2][q].z + hp3*xj[3][q].z;
            bin[q].w = hp0*xj[0][q].w + hp1*xj[1][q].w + hp2*xj[2][q].w + hp3*xj[3][q].w;
        }

#pragma unroll
        for (int i = 0; i < 4; ++i) {
            float hq = hp[20 + i];
#pragma unroll
            for (int q = 0; q < 2; ++q) {
                float4 o;
                o.x = hq*bin[q].x; o.y = hq*bin[q].y;
                o.z = hq*bin[q].z; o.w = hq*bin[q].w;
#pragma unroll
                for (int j = 0; j < 4; ++j) {
                    float h = hp[i*4 + j];
                    o.x += h * xj[j][q].x; o.y += h * xj[j][q].y;
                    o.z += h * xj[j][q].z; o.w += h * xj[j][q].w;
                }
                __stcs((float4*)(yr + i * 1024 + q * 4), o);
            }
        }
    }
#undef STAGE
}

// ============================================================
// launch
// ============================================================
extern "C" void kernel_launch(void* const* d_in, const int* in_sizes, int n_in,
                              void* d_out, int out_size) {
    const float* residuals  = (const float*)d_in[0];
    const float* gamma      = (const float*)d_in[1];
    const float* w_res      = (const float*)d_in[2];
    const float* w_pre      = (const float*)d_in[3];
    const float* w_post     = (const float*)d_in[4];
    const float* beta_res   = (const float*)d_in[5];
    const float* beta_pre   = (const float*)d_in[6];
    const float* beta_post  = (const float*)d_in[7];
    const float* alpha_res  = (const float*)d_in[8];
    const float* alpha_pre  = (const float*)d_in[9];
    const float* alpha_post = (const float*)d_in[10];

    const int nt = in_sizes[0] / KDIM;   // B*T tokens (8192)

    static bool attr_set = false;
    if (!attr_set) {
        cudaFuncSetAttribute(fused_kernel,
                             cudaFuncAttributeMaxDynamicSharedMemorySize,
                             SMEMD);
        attr_set = true;
    }

    prep_kernel<<<(RROWS * (KDIM / 2) + 255) / 256, 256>>>(w_res, w_pre,
                                                           w_post, gamma);
    fused_kernel<<<nt / MTOK, 128, SMEMD>>>(residuals, (float*)d_out,
                                            beta_res, beta_pre, beta_post,
                                            alpha_res, alpha_pre, alpha_post);
}

// round 14
// speedup vs baseline: 1.1013x; 1.1013x over previous
#include <cuda_runtime.h>
#include <math.h>
#include <stdint.h>

#define KDIM   4096
#define RROWS  24
#define MAXNT  8192
#define MTOK   16                 // tokens per block (one m16 tile)
#define NCHM   64                 // chunks of 64 k
#define PFD    4                  // register lookahead (chunks)

// -------- scratch (no cudaMalloc allowed) --------
// repacked weights: for (row r, k16-group w16, tig) the two B-fragment
// words (k pair at w16*16+2tig and +8) are adjacent -> one LDG.64/lane.
__device__ uint32_t g_wP[RROWS * (KDIM / 2)];
__device__ float    g_H [MAXNT * RROWS];

// ---------------- helpers ----------------
__device__ __forceinline__ float ex2f(float x) {
    float r; asm("ex2.approx.f32 %0, %1;" : "=f"(r) : "f"(x)); return r;
}
__device__ __forceinline__ float lg2f(float x) {
    float r; asm("lg2.approx.f32 %0, %1;" : "=f"(r) : "f"(x)); return r;
}
__device__ __forceinline__ uint32_t bf2(float2 v) {
    uint32_t r;
    asm("cvt.rn.bf16x2.f32 %0, %1, %2;" : "=r"(r) : "f"(v.y), "f"(v.x));
    return r;
}
__device__ __forceinline__ uint32_t bf2s(float lo, float hi) {
    uint32_t r;
    asm("cvt.rn.bf16x2.f32 %0, %1, %2;" : "=r"(r) : "f"(hi), "f"(lo));
    return r;
}
__device__ __forceinline__ void mma16(float* c, uint32_t a0, uint32_t a1,
                                      uint32_t a2, uint32_t a3,
                                      uint32_t b0, uint32_t b1) {
    asm volatile(
        "mma.sync.aligned.m16n8k16.row.col.f32.bf16.bf16.f32 "
        "{%0,%1,%2,%3}, {%4,%5,%6,%7}, {%8,%9}, {%0,%1,%2,%3};"
        : "+f"(c[0]), "+f"(c[1]), "+f"(c[2]), "+f"(c[3])
        : "r"(a0), "r"(a1), "r"(a2), "r"(a3), "r"(b0), "r"(b1));
}
#define LOG2E 1.4426950408889634f
__device__ __forceinline__ float lse4_2(float a, float b, float c, float d) {
    float m = fmaxf(fmaxf(a, b), fmaxf(c, d));
    float s = ex2f(a - m) + ex2f(b - m) + ex2f(c - m) + ex2f(d - m);
    return m + lg2f(s);
}

// ============================================================
// K0: fold gamma, pack B-fragment word pairs contiguously.
// idx -> (r, w16, tig): words for k pairs (k0,k0+1) and (k0+8,k0+9),
// k0 = w16*16 + 2*tig, stored at g_wP[idx*2], [idx*2+1].
// ============================================================
__global__ void prep_kernel(const float* __restrict__ w_res,
                            const float* __restrict__ w_pre,
                            const float* __restrict__ w_post,
                            const float* __restrict__ gamma) {
    int idx = blockIdx.x * blockDim.x + threadIdx.x;
    if (idx >= RROWS * 256 * 4) return;
    int r   = idx >> 10;
    int rem = idx & 1023;
    int w16 = rem >> 2;
    int tig = rem & 3;
    int k0  = w16 * 16 + tig * 2;
    const float* src;
    int rr = r;
    if (r < 16)      { src = w_res;  }
    else if (r < 20) { src = w_pre;  rr = r - 16; }
    else             { src = w_post; rr = r - 20; }
    const float* wr = src + (size_t)rr * KDIM;
    g_wP[idx * 2]     = bf2s(wr[k0]     * (1.0f + gamma[k0]),
                             wr[k0 + 1] * (1.0f + gamma[k0 + 1]));
    g_wP[idx * 2 + 1] = bf2s(wr[k0 + 8] * (1.0f + gamma[k0 + 8]),
                             wr[k0 + 9] * (1.0f + gamma[k0 + 9]));
}

// ============================================================
// K1: dots + heads, NO smem pipeline. 512 blocks x 128 threads.
// Warp = one K-quarter of each 64k chunk; all warps share the 16-token
// m-tile. A and B fragments LDG'd straight to registers, 4-chunk
// lookahead. Epilogue: combine 4 K-quarter partials in (tiny) smem,
// then warp 0 computes sinkhorn/softmax/sigmoid heads -> g_H.
// ============================================================
__global__ void __launch_bounds__(128)
dots_heads(const float* __restrict__ x,
           const float* __restrict__ beta_res,
           const float* __restrict__ beta_pre,
           const float* __restrict__ beta_post,
           const float* __restrict__ alpha_res,
           const float* __restrict__ alpha_pre,
           const float* __restrict__ alpha_post) {
    __shared__ float sP[4][MTOK * RROWS];
    __shared__ float sQ[4][MTOK];

    const int tid  = threadIdx.x;
    const int lane = tid & 31;
    const int grp  = tid >> 5;            // K-quarter 0..3
    const int g    = lane >> 2;           // 0..7
    const int tig  = lane & 3;            // 0..3
    const int tokb = blockIdx.x * MTOK;

    const float* x0 = x + (size_t)(tokb + g) * KDIM + grp * 16 + tig * 2;
    const float* x1 = x0 + 8 * KDIM;
    const uint32_t* wp = g_wP + g * 2048 + grp * 8 + tig * 2;
    // per-chunk advance: x += 64 floats, wp += 32 u32 (4 k16-groups)
    // nt stride: 8 rows * 2048 u32 = 16384 u32

    float2 A[PFD][4];
    uint2  Bf[PFD][3];
    float acc[3][4];
#pragma unroll
    for (int nt = 0; nt < 3; ++nt)
#pragma unroll
        for (int i = 0; i < 4; ++i) acc[nt][i] = 0.0f;
    float ssq0 = 0.0f, ssq1 = 0.0f;

#define LDGCH(b) do {                                                          \
        A[b][0] = *(const float2*)(x0);                                        \
        A[b][1] = *(const float2*)(x1);                                        \
        A[b][2] = *(const float2*)(x0 + 8);                                    \
        A[b][3] = *(const float2*)(x1 + 8);                                    \
        Bf[b][0] = *(const uint2*)(wp);                                        \
        Bf[b][1] = *(const uint2*)(wp + 16384);                                \
        Bf[b][2] = *(const uint2*)(wp + 32768);                                \
        x0 += 64; x1 += 64; wp += 32;                                          \
    } while (0)

    LDGCH(0); LDGCH(1); LDGCH(2); LDGCH(3);

    for (int ch = 0; ch < NCHM; ch += PFD) {
        const bool pf = (ch + PFD < NCHM);
#pragma unroll
        for (int u = 0; u < PFD; ++u) {
            float2 f0 = A[u][0], f1 = A[u][1], f2 = A[u][2], f3 = A[u][3];
            ssq0 = fmaf(f0.x, f0.x, fmaf(f0.y, f0.y,
                   fmaf(f2.x, f2.x, fmaf(f2.y, f2.y, ssq0))));
            ssq1 = fmaf(f1.x, f1.x, fmaf(f1.y, f1.y,
                   fmaf(f3.x, f3.x, fmaf(f3.y, f3.y, ssq1))));
            uint32_t A0 = bf2(f0), A1 = bf2(f1), A2 = bf2(f2), A3 = bf2(f3);
            uint2 b0 = Bf[u][0], b1 = Bf[u][1], b2 = Bf[u][2];
            mma16(acc[0], A0, A1, A2, A3, b0.x, b0.y);
            mma16(acc[1], A0, A1, A2, A3, b1.x, b1.y);
            mma16(acc[2], A0, A1, A2, A3, b2.x, b2.y);
            if (pf) LDGCH(u);
        }
    }
#undef LDGCH

    // ---- quad-reduce ssq over tig ----
    ssq0 += __shfl_down_sync(0xffffffffu, ssq0, 2, 4);
    ssq0 += __shfl_down_sync(0xffffffffu, ssq0, 1, 4);
    ssq1 += __shfl_down_sync(0xffffffffu, ssq1, 2, 4);
    ssq1 += __shfl_down_sync(0xffffffffu, ssq1, 1, 4);

    // ---- write K-quarter partials ----
#pragma unroll
    for (int nt = 0; nt < 3; ++nt) {
        int r = nt * 8 + 2 * tig;
        *(float2*)&sP[grp][g * RROWS + r] =
            make_float2(acc[nt][0], acc[nt][1]);
        *(float2*)&sP[grp][(g + 8) * RROWS + r] =
            make_float2(acc[nt][2], acc[nt][3]);
    }
    if (tig == 0) { sQ[grp][g] = ssq0; sQ[grp][g + 8] = ssq1; }
    __syncthreads();

    // ---- combine 4 quarters: 384 dot values, 3 per thread ----
#pragma unroll
    for (int j = 0; j < 3; ++j) {
        int i = tid + 128 * j;
        sP[0][i] = sP[0][i] + sP[1][i] + sP[2][i] + sP[3][i];
    }
    if (tid < MTOK)
        sQ[0][tid] = sQ[0][tid] + sQ[1][tid] + sQ[2][tid] + sQ[3][tid];
    __syncthreads();

    // ---- heads: threads 0..15, one token each ----
    if (tid < MTOK) {
        const int t = tid;
        float rstd = 64.0f / fmaxf(sqrtf(sQ[0][t]), 1e-12f);
        const float* dp = &sP[0][t * RROWS];
        float ar = alpha_res[0]  * rstd;
        float ap = alpha_pre[0]  * rstd;
        float ao = alpha_post[0] * rstd;

        float Z[16];
#pragma unroll
        for (int e = 0; e < 16; ++e)
            Z[e] = (beta_res[e] + ar * dp[e]) * (20.0f * LOG2E);

        float u[4] = {0.f, 0.f, 0.f, 0.f};
        float v[4] = {0.f, 0.f, 0.f, 0.f};
#pragma unroll 1
        for (int itn = 0; itn < 10; ++itn) {
#pragma unroll
            for (int i = 0; i < 4; ++i)
                u[i] = -lse4_2(Z[i*4+0] + v[0], Z[i*4+1] + v[1],
                               Z[i*4+2] + v[2], Z[i*4+3] + v[3]);
#pragma unroll
            for (int j = 0; j < 4; ++j)
                v[j] = -lse4_2(Z[0*4+j] + u[0], Z[1*4+j] + u[1],
                               Z[2*4+j] + u[2], Z[3*4+j] + u[3]);
        }

        float* hp = g_H + (size_t)(tokb + t) * RROWS;
#pragma unroll
        for (int i = 0; i < 4; ++i)
#pragma unroll
            for (int j = 0; j < 4; ++j)
                hp[i*4+j] = ex2f(Z[i*4+j] + u[i] + v[j]);

        float p[4];
#pragma unroll
        for (int s = 0; s < 4; ++s)
            p[s] = (beta_pre[s] + ap * dp[16 + s]) * LOG2E;
        float m = fmaxf(fmaxf(p[0], p[1]), fmaxf(p[2], p[3]));
        float e0 = ex2f(p[0]-m), e1 = ex2f(p[1]-m);
        float e2 = ex2f(p[2]-m), e3 = ex2f(p[3]-m);
        float inv = 1.0f / (e0 + e1 + e2 + e3);
        hp[16] = e0*inv; hp[17] = e1*inv; hp[18] = e2*inv; hp[19] = e3*inv;

#pragma unroll
        for (int s = 0; s < 4; ++s) {
            float q = beta_post[s] + ao * dp[20 + s];
            hp[20 + s] = 2.0f / (1.0f + ex2f(-q * LOG2E));
        }
    }
}

// ============================================================
// K2: out[i,d] = sum_j Hres[i][j] x[j,d] + Hpost[i] * sum_s Hpre[s] x[s,d]
// ============================================================
#define D4 1024
__global__ void __launch_bounds__(256)
mix_kernel(const float* __restrict__ x, float* __restrict__ out) {
    const int tok = blockIdx.x;
    const float* xr = x   + (size_t)tok * KDIM;
    float*       yr = out + (size_t)tok * KDIM;
    const float* hp = g_H + (size_t)tok * RROWS;

    float hres[16], hpre[4], hpost[4];
#pragma unroll
    for (int e = 0; e < 16; ++e) hres[e] = __ldg(hp + e);
#pragma unroll
    for (int s = 0; s < 4; ++s)  hpre[s]  = __ldg(hp + 16 + s);
#pragma unroll
    for (int s = 0; s < 4; ++s)  hpost[s] = __ldg(hp + 20 + s);

    const int col = threadIdx.x * 4;
    float4 xj[4];
#pragma unroll
    for (int j = 0; j < 4; ++j)
        xj[j] = __ldcs((const float4*)(xr + j * D4 + col));

    float4 bin;
    bin.x = hpre[0]*xj[0].x + hpre[1]*xj[1].x + hpre[2]*xj[2].x + hpre[3]*xj[3].x;
    bin.y = hpre[0]*xj[0].y + hpre[1]*xj[1].y + hpre[2]*xj[2].y + hpre[3]*xj[3].y;
    bin.z = hpre[0]*xj[0].z + hpre[1]*xj[1].z + hpre[2]*xj[2].z + hpre[3]*xj[3].z;
    bin.w = hpre[0]*xj[0].w + hpre[1]*xj[1].w + hpre[2]*xj[2].w + hpre[3]*xj[3].w;

#pragma unroll
    for (int i = 0; i < 4; ++i) {
        float4 o;
        o.x = hpost[i]*bin.x; o.y = hpost[i]*bin.y;
        o.z = hpost[i]*bin.z; o.w = hpost[i]*bin.w;
#pragma unroll
        for (int j = 0; j < 4; ++j) {
            float h = hres[i*4 + j];
            o.x += h * xj[j].x; o.y += h * xj[j].y;
            o.z += h * xj[j].z; o.w += h * xj[j].w;
        }
        __stcs((float4*)(yr + i * D4 + col), o);
    }
}

// ============================================================
// launch
// ============================================================
extern "C" void kernel_launch(void* const* d_in, const int* in_sizes, int n_in,
                              void* d_out, int out_size) {
    const float* residuals  = (const float*)d_in[0];
    const float* gamma      = (const float*)d_in[1];
    const float* w_res      = (const float*)d_in[2];
    const float* w_pre      = (const float*)d_in[3];
    const float* w_post     = (const float*)d_in[4];
    const float* beta_res   = (const float*)d_in[5];
    const float* beta_pre   = (const float*)d_in[6];
    const float* beta_post  = (const float*)d_in[7];
    const float* alpha_res  = (const float*)d_in[8];
    const float* alpha_pre  = (const float*)d_in[9];
    const float* alpha_post = (const float*)d_in[10];

    const int nt = in_sizes[0] / KDIM;   // B*T tokens (8192)

    prep_kernel<<<(RROWS * 1024 + 255) / 256, 256>>>(w_res, w_pre,
                                                     w_post, gamma);
    dots_heads<<<nt / MTOK, 128>>>(residuals,
                                   beta_res, beta_pre, beta_post,
                                   alpha_res, alpha_pre, alpha_post);
    mix_kernel<<<nt, 256>>>(residuals, (float*)d_out);
}